// round 13
// baseline (speedup 1.0000x reference)
#include <cuda_runtime.h>

// feature_map [512,512,64] f32, boxes [512,4] f32 (cx,cy,w,h), out [512,32,32,64] f32
#define IN_H    512
#define IN_W    512
#define NC4     16          // channels as float4 groups (2 f32x2 pairs each)
#define NBOX    512
#define OUTW    32
#define OYT     8           // oy rows per CTA tile (minimal row overlap)
#define NTILES  (OUTW / OYT)
#define MAXTAPS 36          // ks < 16 -> taps <= 34
#define MAXROWS 152         // union of 8 oy windows: 7*inv + 2ks + 2 < 146

typedef unsigned long long ull;

// packed dual-FMA: acc.lane += v.lane * w.lane  (IEEE f32 per lane)
#define FMA2(acc, v, w) \
    asm("fma.rn.f32x2 %0, %1, %2, %0;" : "+l"(acc) : "l"(v), "l"(w))

// One CTA per (box, oy-tile of 8). 512 threads = 32 ox x 16 c4 lanes.
// Reads the f32 feature map directly (no fp16 staging, no F2F tax):
// per tap one LDG.128 covers 4 channels as two packed f32x2 operands.
// Each thread x-filters each union row once, scatters into 8 oy
// accumulator pairs with SMEM y-weights. 64-reg / 2-CTA operating point.
// Weight math replicates jax.image.scale_and_translate(method="linear",
// antialias=True) exactly (formulas verified since R4).
__global__ __launch_bounds__(512, 2)
void roi_align_kernel(const float* __restrict__ fm,
                      const float* __restrict__ boxes,
                      float* __restrict__ out)
{
    __shared__ float2 s_wx2[OUTW * MAXTAPS];    // x weights, duplicated {w,w}
    __shared__ int    s_xb[OUTW];               // x window base per ox
    __shared__ float  s_sy[OYT];                // y sample pos per tile oy
    __shared__ float  s_invn[OYT];              // y norm (0 if invalid)
    __shared__ int    s_yb[OYT];                // y window base per tile oy
    __shared__ float2 s_wyt2[MAXROWS * OYT];    // y weights, duplicated {w,w}

    const int tile = blockIdx.x;   // 0..3
    const int box  = blockIdx.y;   // 0..511
    const int tid  = threadIdx.x;

    // ---- box parameters (all threads) ----
    const float4 b = ((const float4*)boxes)[box];
    float x0 = b.x - b.z * 0.5f;           // pre-clamp w/h (reference order)
    float y0 = b.y - b.w * 0.5f;
    float bw = fmaxf(b.z, 1e-6f);
    float bh = fmaxf(b.w, 1e-6f);

    float scale_x = 32.0f / (bw * 512.0f);
    float inv_x   = 1.0f / scale_x;
    float ks_x    = fmaxf(inv_x, 1.0f);
    float toff_x  = ((-x0 * 32.0f) / bw) * inv_x;
    int   ntx     = min((int)(2.0f * ks_x) + 2, 34);

    float scale_y = 32.0f / (bh * 512.0f);
    float inv_y   = 1.0f / scale_y;
    float ks_y    = fmaxf(inv_y, 1.0f);
    float toff_y  = ((-y0 * 32.0f) / bh) * inv_y;
    int   nty     = min((int)(2.0f * ks_y) + 2, 34);
    float rks_y   = 1.0f / ks_y;

    // ---- phase 1: per-ox x weights (threads 0..31), per-oy y params (32..39)
    if (tid < OUTW) {
        const int ox = tid;
        float s    = ((float)ox + 0.5f) * inv_x - toff_x - 0.5f;
        int   base = min(max((int)ceilf(s - ks_x), 0), IN_W - ntx);
        float rks  = 1.0f / ks_x;
        float norm = 0.0f;
        for (int j = 0; j < ntx; j++)
            norm += fmaxf(0.0f, 1.0f - fabsf(s - (float)(base + j)) * rks);
        bool valid = (s >= -0.5f) && (s <= (float)IN_W - 0.5f)
                     && (fabsf(norm) > 1.1920929e-4f);   // 1000 * eps_f32
        float invn = valid ? (1.0f / norm) : 0.0f;
        for (int j = 0; j < ntx; j++) {
            float w = fmaxf(0.0f, 1.0f - fabsf(s - (float)(base + j)) * rks) * invn;
            s_wx2[ox * MAXTAPS + j] = make_float2(w, w);
        }
        s_xb[ox] = base;
    } else if (tid < OUTW + OYT) {
        const int k  = tid - OUTW;
        const int oy = tile * OYT + k;
        float sy = ((float)oy + 0.5f) * inv_y - toff_y - 0.5f;
        int   yb = min(max((int)ceilf(sy - ks_y), 0), IN_H - nty);
        float norm = 0.0f;
        for (int j = 0; j < nty; j++)
            norm += fmaxf(0.0f, 1.0f - fabsf(sy - (float)(yb + j)) * rks_y);
        bool valid = (sy >= -0.5f) && (sy <= (float)IN_H - 0.5f)
                     && (fabsf(norm) > 1.1920929e-4f);
        s_sy[k]   = sy;
        s_invn[k] = valid ? (1.0f / norm) : 0.0f;
        s_yb[k]   = yb;
    }
    __syncthreads();

    // ---- phase 2: fill duplicated wy table over the row union ----
    const int rmin   = s_yb[0];                       // sy monotone in k
    const int rcount = s_yb[OYT - 1] + nty - rmin;    // <= 146
    for (int idx = tid; idx < rcount * OYT; idx += 512) {
        int r = idx >> 3, k = idx & (OYT - 1);
        float w = fmaxf(0.0f, 1.0f - fabsf(s_sy[k] - (float)(rmin + r)) * rks_y)
                  * s_invn[k];
        s_wyt2[idx] = make_float2(w, w);
    }
    __syncthreads();

    // active rows form one interval (y-windows of the 8 oy overlap)
    const int rlo = max(rmin, (int)ceilf(s_sy[0] - ks_y));
    const int rhi = min(rmin + rcount, (int)floorf(s_sy[OYT - 1] + ks_y) + 1);

    // ---- main loop: thread = (ox, c4), 8 oy f32x2-pair accumulators ----
    const int ox = tid >> 4;        // 0..31
    const int c4 = tid & 15;        // 0..15
    const ulonglong2* __restrict__ wxp =
        (const ulonglong2*)&s_wx2[ox * MAXTAPS];   // 16B-aligned weight pairs
    const int np   = ntx >> 1;      // full tap pairs
    const int todd = ntx & 1;       // one guarded tail tap (uniform in CTA)

    ull a01_0 = 0, a23_0 = 0, a01_1 = 0, a23_1 = 0;
    ull a01_2 = 0, a23_2 = 0, a01_3 = 0, a23_3 = 0;
    ull a01_4 = 0, a23_4 = 0, a01_5 = 0, a23_5 = 0;
    ull a01_6 = 0, a23_6 = 0, a01_7 = 0, a23_7 = 0;

    // feature map as packed f32x2 pairs: one float4 = ulonglong2{ch01, ch23}
    const ulonglong2* __restrict__ rowp =
        (const ulonglong2*)fm + ((size_t)rlo * IN_W + s_xb[ox]) * NC4 + c4;
    const ulonglong2* __restrict__ wyp =
        (const ulonglong2*)&s_wyt2[(rlo - rmin) * OYT];

    for (int r = rlo; r < rhi; r++) {
        // x convolution: pairs of taps, both LDG.128 issued before the FMAs
        ull r01 = 0, r23 = 0;
        const ulonglong2* __restrict__ p = rowp;
        for (int jp = 0; jp < np; jp++) {
            ulonglong2 v0 = p[0];
            ulonglong2 v1 = p[NC4];
            ulonglong2 w01 = wxp[jp];          // LDS.128: 2 duplicated weights
            FMA2(r01, v0.x, w01.x);
            FMA2(r23, v0.y, w01.x);
            FMA2(r01, v1.x, w01.y);
            FMA2(r23, v1.y, w01.y);
            p += 2 * NC4;
        }
        if (todd) {                            // last tap of an odd window
            ulonglong2 v0 = p[0];
            ull w = *(const ull*)&s_wx2[ox * MAXTAPS + ntx - 1];
            FMA2(r01, v0.x, w);
            FMA2(r23, v0.y, w);
        }

        // scatter into 8 oy accumulators; wy pairs via 4 x LDS.128
        ulonglong2 wy01 = wyp[0];
        ulonglong2 wy23 = wyp[1];
        ulonglong2 wy45 = wyp[2];
        ulonglong2 wy67 = wyp[3];
        FMA2(a01_0, r01, wy01.x);  FMA2(a23_0, r23, wy01.x);
        FMA2(a01_1, r01, wy01.y);  FMA2(a23_1, r23, wy01.y);
        FMA2(a01_2, r01, wy23.x);  FMA2(a23_2, r23, wy23.x);
        FMA2(a01_3, r01, wy23.y);  FMA2(a23_3, r23, wy23.y);
        FMA2(a01_4, r01, wy45.x);  FMA2(a23_4, r23, wy45.x);
        FMA2(a01_5, r01, wy45.y);  FMA2(a23_5, r23, wy45.y);
        FMA2(a01_6, r01, wy67.x);  FMA2(a23_6, r23, wy67.x);
        FMA2(a01_7, r01, wy67.y);  FMA2(a23_7, r23, wy67.y);

        rowp += IN_W * NC4;
        wyp  += 4;              // OYT pairs per row = 4 ulonglong2
    }

    // ---- write out[box][tile*8+k][ox][c] ----
    {
        float2* __restrict__ out2 = (float2*)out;
        size_t base =
            ((((size_t)box * OUTW + tile * OYT) * OUTW + ox) * NC4 + c4) * 2;
        const size_t st = (size_t)OUTW * NC4 * 2;
        out2[base + 0]      = *reinterpret_cast<float2*>(&a01_0);
        out2[base + 1]      = *reinterpret_cast<float2*>(&a23_0);
        out2[base + st + 0] = *reinterpret_cast<float2*>(&a01_1);
        out2[base + st + 1] = *reinterpret_cast<float2*>(&a23_1);
        out2[base + 2*st + 0] = *reinterpret_cast<float2*>(&a01_2);
        out2[base + 2*st + 1] = *reinterpret_cast<float2*>(&a23_2);
        out2[base + 3*st + 0] = *reinterpret_cast<float2*>(&a01_3);
        out2[base + 3*st + 1] = *reinterpret_cast<float2*>(&a23_3);
        out2[base + 4*st + 0] = *reinterpret_cast<float2*>(&a01_4);
        out2[base + 4*st + 1] = *reinterpret_cast<float2*>(&a23_4);
        out2[base + 5*st + 0] = *reinterpret_cast<float2*>(&a01_5);
        out2[base + 5*st + 1] = *reinterpret_cast<float2*>(&a23_5);
        out2[base + 6*st + 0] = *reinterpret_cast<float2*>(&a01_6);
        out2[base + 6*st + 1] = *reinterpret_cast<float2*>(&a23_6);
        out2[base + 7*st + 0] = *reinterpret_cast<float2*>(&a01_7);
        out2[base + 7*st + 1] = *reinterpret_cast<float2*>(&a23_7);
    }
}

extern "C" void kernel_launch(void* const* d_in, const int* in_sizes, int n_in,
                              void* d_out, int out_size)
{
    const float* fm    = (const float*)d_in[0];   // [512, 512, 64] f32
    const float* boxes = (const float*)d_in[1];   // [512, 4] f32
    float* out = (float*)d_out;                   // [512, 32, 32, 64] f32

    dim3 grid(NTILES, NBOX);   // (oy-tile, box) -> 2048 CTAs
    roi_align_kernel<<<grid, 512>>>(fm, boxes, out);
}